// round 11
// baseline (speedup 1.0000x reference)
#include <cuda_runtime.h>

// KVQuantizerDequantizer: asymmetric 4-bit RTN quantize+dequantize, groups of
// 128 floats along last dim. At the measured mixed 1:1 r/w DRAM ceiling
// (~6.44 TB/s). This round: Blackwell 256-bit vector memory ops
// (ld/st.global.v8.f32) — halves LSU instructions and L1tex wavefront
// entries per byte; geometry otherwise identical to the converged config
// (8 lanes/group, 4 groups/warp, 16 floats/thread, non-persistent launch).

#define MAXQ 15.0f
#define EPS 1e-8f

struct V8 { float f[8]; };

__device__ __forceinline__ V8 ldg256(const float* p) {
    V8 v;
    asm volatile("ld.global.v8.f32 {%0,%1,%2,%3,%4,%5,%6,%7}, [%8];"
                 : "=f"(v.f[0]), "=f"(v.f[1]), "=f"(v.f[2]), "=f"(v.f[3]),
                   "=f"(v.f[4]), "=f"(v.f[5]), "=f"(v.f[6]), "=f"(v.f[7])
                 : "l"(p));
    return v;
}

__device__ __forceinline__ void stg256(float* p, const V8& v) {
    asm volatile("st.global.v8.f32 [%0], {%1,%2,%3,%4,%5,%6,%7,%8};"
                 :: "l"(p),
                    "f"(v.f[0]), "f"(v.f[1]), "f"(v.f[2]), "f"(v.f[3]),
                    "f"(v.f[4]), "f"(v.f[5]), "f"(v.f[6]), "f"(v.f[7])
                 : "memory");
}

__global__ void __launch_bounds__(256, 8)
kvq_kernel(const float* __restrict__ x, float* __restrict__ out, unsigned n_groups) {
    const unsigned lane = threadIdx.x & 31u;
    const unsigned sl   = lane & 7u;            // lane within 8-lane octet
    const unsigned warp_global = blockIdx.x * (blockDim.x >> 5) + (threadIdx.x >> 5);
    const unsigned group = warp_global * 4u + (lane >> 3);
    if (group >= n_groups) return;

    const float* gbase = x + (size_t)group * 128u;

    // 2 independent 256-bit loads, front-batched.
    // lo covers elements [sl*8, sl*8+8) of the first 64; hi the second 64.
    V8 lo = ldg256(gbase + sl * 8u);
    V8 hi = ldg256(gbase + 64u + sl * 8u);

    // local min/max over 16 values
    float mn = lo.f[0], mx = lo.f[0];
    #pragma unroll
    for (int i = 1; i < 8; i++) { mn = fminf(mn, lo.f[i]); mx = fmaxf(mx, lo.f[i]); }
    #pragma unroll
    for (int i = 0; i < 8; i++) { mn = fminf(mn, hi.f[i]); mx = fmaxf(mx, hi.f[i]); }

    // butterfly within the 8-lane octet (xor 1,2,4 stays inside)
    #pragma unroll
    for (int off = 1; off < 8; off <<= 1) {
        mn = fminf(mn, __shfl_xor_sync(0xffffffffu, mn, off));
        mx = fmaxf(mx, __shfl_xor_sync(0xffffffffu, mx, off));
    }

    // scale / offset (CLIP_RATIO = 1.0); one true division per thread
    const float scale  = fmaxf((mx - mn) / MAXQ, EPS);
    const float rscale = 1.0f / scale;
    const float offset = rintf(-mn * rscale);

    // quantize + dequantize (rintf == jnp.round: round-half-to-even under RN)
    #pragma unroll
    for (int i = 0; i < 8; i++) {
        float q = fminf(fmaxf(rintf(lo.f[i] * rscale) + offset, 0.0f), MAXQ);
        lo.f[i] = (q - offset) * scale;
    }
    #pragma unroll
    for (int i = 0; i < 8; i++) {
        float q = fminf(fmaxf(rintf(hi.f[i] * rscale) + offset, 0.0f), MAXQ);
        hi.f[i] = (q - offset) * scale;
    }

    float* obase = out + (size_t)group * 128u;
    stg256(obase + sl * 8u, lo);
    stg256(obase + 64u + sl * 8u, hi);
}

extern "C" void kernel_launch(void* const* d_in, const int* in_sizes, int n_in,
                              void* d_out, int out_size) {
    const float* x = (const float*)d_in[0];
    float* out = (float*)d_out;

    unsigned n_groups = (unsigned)((long long)in_sizes[0] / 128);  // 524288

    const int threads = 256;                   // 8 warps -> 32 groups per block
    unsigned groups_per_block = (threads / 32) * 4;
    unsigned blocks = (n_groups + groups_per_block - 1) / groups_per_block;

    kvq_kernel<<<blocks, threads>>>(x, out, n_groups);
}

// round 12
// speedup vs baseline: 1.0051x; 1.0051x over previous
#include <cuda_runtime.h>

// KVQuantizerDequantizer: asymmetric 4-bit RTN quantize+dequantize, groups of
// 128 floats along last dim. FINAL — converged at the measured mixed 1:1
// read/write DRAM ceiling (6.42-6.45 TB/s; 537 MB mandatory traffic in
// ~74.5us kernel time, zero wasted bytes).
//
// Convergence evidence (11 rounds): MLP 1/4/8, occupancy 48-84%, block
// 128/256, load ca/cg/cs, store wb/cs, 128b/256b accesses, multi-wave vs
// persistent vs SW-pipelined — every non-regressive config clamps at the
// same bandwidth. Best-measured config below (bench 81.98us x2, ncu 74.43us):
//  - non-persistent launch: CTA scheduler provides load/store overlap free
//    (persistent variants measured 8-11% WORSE)
//  - 8 lanes per group, 4 groups per warp, 4 front-batched float4 loads
//  - default-cached loads, plain writeback stores
//  - 32 regs, 256 threads, occupancy 8 blocks/SM

#define MAXQ 15.0f
#define EPS 1e-8f

__global__ void __launch_bounds__(256, 8)
kvq_kernel(const float* __restrict__ x, float* __restrict__ out, unsigned n_groups) {
    const unsigned lane = threadIdx.x & 31u;
    const unsigned sl   = lane & 7u;            // lane within 8-lane octet
    const unsigned warp_global = blockIdx.x * (blockDim.x >> 5) + (threadIdx.x >> 5);
    const unsigned group = warp_global * 4u + (lane >> 3);
    if (group >= n_groups) return;

    const float4* gp = reinterpret_cast<const float4*>(x) + (size_t)group * 32u;

    // 4 independent loads, front-batched (MLP=4)
    float4 a = gp[sl];
    float4 b = gp[sl + 8];
    float4 c = gp[sl + 16];
    float4 d = gp[sl + 24];

    // local min/max over 16 values
    float mn = fminf(fminf(fminf(a.x, a.y), fminf(a.z, a.w)),
                     fminf(fminf(b.x, b.y), fminf(b.z, b.w)));
    mn = fminf(mn, fminf(fminf(fminf(c.x, c.y), fminf(c.z, c.w)),
                         fminf(fminf(d.x, d.y), fminf(d.z, d.w))));
    float mx = fmaxf(fmaxf(fmaxf(a.x, a.y), fmaxf(a.z, a.w)),
                     fmaxf(fmaxf(b.x, b.y), fmaxf(b.z, b.w)));
    mx = fmaxf(mx, fmaxf(fmaxf(fmaxf(c.x, c.y), fmaxf(c.z, c.w)),
                         fmaxf(fmaxf(d.x, d.y), fmaxf(d.z, d.w))));

    // butterfly within the 8-lane octet (xor 1,2,4 stays inside)
    #pragma unroll
    for (int off = 1; off < 8; off <<= 1) {
        mn = fminf(mn, __shfl_xor_sync(0xffffffffu, mn, off));
        mx = fmaxf(mx, __shfl_xor_sync(0xffffffffu, mx, off));
    }

    // scale / offset (CLIP_RATIO = 1.0); one true division per thread
    const float scale  = fmaxf((mx - mn) / MAXQ, EPS);
    const float rscale = 1.0f / scale;
    const float offset = rintf(-mn * rscale);

    // quantize + dequantize (rintf == jnp.round: round-half-to-even under RN)
    #define QDQ(e) do { \
        float q = fminf(fmaxf(rintf((e) * rscale) + offset, 0.0f), MAXQ); \
        (e) = (q - offset) * scale; \
    } while (0)
    QDQ(a.x); QDQ(a.y); QDQ(a.z); QDQ(a.w);
    QDQ(b.x); QDQ(b.y); QDQ(b.z); QDQ(b.w);
    QDQ(c.x); QDQ(c.y); QDQ(c.z); QDQ(c.w);
    QDQ(d.x); QDQ(d.y); QDQ(d.z); QDQ(d.w);
    #undef QDQ

    float4* og = reinterpret_cast<float4*>(out) + (size_t)group * 32u;
    og[sl]      = a;
    og[sl + 8]  = b;
    og[sl + 16] = c;
    og[sl + 24] = d;
}

extern "C" void kernel_launch(void* const* d_in, const int* in_sizes, int n_in,
                              void* d_out, int out_size) {
    const float* x = (const float*)d_in[0];
    float* out = (float*)d_out;

    unsigned n_groups = (unsigned)((long long)in_sizes[0] / 128);  // 524288

    const int threads = 256;                   // 8 warps -> 32 groups per block
    unsigned groups_per_block = (threads / 32) * 4;
    unsigned blocks = (n_groups + groups_per_block - 1) / groups_per_block;

    kvq_kernel<<<blocks, threads>>>(x, out, n_groups);
}